// round 3
// baseline (speedup 1.0000x reference)
#include <cuda_runtime.h>
#include <cuda_bf16.h>
#include <cstdint>

// ============================================================================
// MultiSimilarityLoss on GB300 (sm_103a; PTX target compute_103 -> no tcgen05;
// mma.sync bf16 HMMA + ldmatrix + cp.async)
//   sim = E @ E^T  (4096x512 fp32, L2-normalized)
//   fused masked-exp epilogue -> per-row pos/neg sums -> log1p -> mean
// ============================================================================

#define N_EMB   4096
#define D_EMB   512
#define MTILE   128
#define NTILE   128
#define KCH     64            // K chunk (64 bf16 = 128B rows)
#define NCHUNKS (D_EMB / KCH) // 8
#define NTHREADS 256

// Scratch (no cudaMalloc allowed)
__device__ __nv_bfloat16 g_eb[N_EMB * D_EMB];
__device__ float g_pos[N_EMB];
__device__ float g_neg[N_EMB];
__device__ int   g_lab[N_EMB];

// smem: labels (1KB) + 2 double-buffered A/B tiles (4 x 16KB)
#define SM_LABELS  0
#define SM_TILES   1024
#define TILE_BYTES 16384                 // 128 rows x 128B
#define SM_TOTAL   (1024 + 4 * TILE_BYTES)  // 66560

__device__ __forceinline__ uint32_t smem_u32(const void* p) {
    uint32_t a;
    asm("{ .reg .u64 t; cvta.to.shared.u64 t, %1; cvt.u32.u64 %0, t; }" : "=r"(a) : "l"(p));
    return a;
}

__device__ __forceinline__ uint32_t sw128(uint32_t off) {
    return off ^ ((off >> 3) & 0x70);
}

__device__ __forceinline__ void ldsm_x4(uint32_t* r, uint32_t addr) {
    asm volatile("ldmatrix.sync.aligned.m8n8.x4.shared.b16 {%0,%1,%2,%3}, [%4];"
                 : "=r"(r[0]), "=r"(r[1]), "=r"(r[2]), "=r"(r[3]) : "r"(addr));
}

__device__ __forceinline__ void mma16816(float* d, const uint32_t* a, uint32_t b0, uint32_t b1) {
    asm volatile(
        "mma.sync.aligned.m16n8k16.row.col.f32.bf16.bf16.f32 "
        "{%0,%1,%2,%3}, {%4,%5,%6,%7}, {%8,%9}, {%0,%1,%2,%3};"
        : "+f"(d[0]), "+f"(d[1]), "+f"(d[2]), "+f"(d[3])
        : "r"(a[0]), "r"(a[1]), "r"(a[2]), "r"(a[3]), "r"(b0), "r"(b1));
}

__device__ __forceinline__ void cp16(uint32_t dst, const void* src) {
    asm volatile("cp.async.cg.shared.global [%0], [%1], 16;" :: "r"(dst), "l"(src));
}

// ============================================================================
// Kernel 0a: labels — dtype-agnostic decode (JAX x64-disable makes the
// "int64" labels actually int32; detect and handle both).
// ============================================================================
__global__ void ms_labels(const void* __restrict__ raw) {
    __shared__ int s_not64;
    const int* r32 = (const int*)raw;
    int t = threadIdx.x;
    if (t == 0) s_not64 = 0;
    __syncthreads();
    // If int64 little-endian with labels in [0,64): odd dwords are all 0.
    int nz = 0;
    for (int i = t; i < N_EMB / 2; i += 256)
        nz |= r32[2 * i + 1];
    if (nz) atomicOr(&s_not64, 1);
    __syncthreads();
    bool is64 = (s_not64 == 0);
    if (is64) {
        const long long* r64 = (const long long*)raw;
        for (int i = t; i < N_EMB; i += 256) g_lab[i] = (int)r64[i];
    } else {
        for (int i = t; i < N_EMB; i += 256) g_lab[i] = r32[i];
    }
}

// ============================================================================
// Kernel 0b: prep — fp32 -> bf16, zero accumulators
// ============================================================================
__global__ void ms_prep(const float* __restrict__ emb) {
    int g = blockIdx.x * blockDim.x + threadIdx.x;
    int stride = gridDim.x * blockDim.x;
    const float4* src = (const float4*)emb;
    __nv_bfloat162* dst = (__nv_bfloat162*)g_eb;
    for (int i = g; i < N_EMB * D_EMB / 4; i += stride) {
        float4 v = src[i];
        dst[2 * i]     = __floats2bfloat162_rn(v.x, v.y);
        dst[2 * i + 1] = __floats2bfloat162_rn(v.z, v.w);
    }
    if (g < N_EMB) { g_pos[g] = 0.f; g_neg[g] = 0.f; }
}

// ============================================================================
// Kernel 1: main — 128x128 sim tile per CTA, fused masked-exp epilogue
// ============================================================================
__global__ __launch_bounds__(NTHREADS) void ms_main() {
    extern __shared__ char smem[];
    int* collab = (int*)(smem + SM_LABELS);        // 128 ints
    int* rowlab = (int*)(smem + SM_LABELS + 512);  // 128 ints
    char* tiles = smem + SM_TILES;

    const int tid  = threadIdx.x;
    const int wid  = tid >> 5;
    const int lane = tid & 31;
    const int wm   = wid & 3;   // 0..3 -> M offset wm*32
    const int wn   = wid >> 2;  // 0..1 -> N offset wn*64
    const int colbase = blockIdx.x * NTILE;
    const int rowbase = blockIdx.y * MTILE;

    if (tid < 128) collab[tid] = g_lab[colbase + tid];
    else           rowlab[tid - 128] = g_lab[rowbase + tid - 128];

    const __nv_bfloat16* gA = g_eb + (size_t)rowbase * D_EMB;
    const __nv_bfloat16* gB = g_eb + (size_t)colbase * D_EMB;

    // ---- issue chunk 0 loads ----
    {
        char* bufA = tiles;
        char* bufB = tiles + TILE_BYTES;
        #pragma unroll
        for (int i = 0; i < 4; i++) {
            int idx = tid + i * NTHREADS;
            int row = idx >> 3, s = idx & 7;
            uint32_t off = sw128((uint32_t)(row * 128 + s * 16));
            cp16(smem_u32(bufA + off), gA + (size_t)row * D_EMB + s * 8);
            cp16(smem_u32(bufB + off), gB + (size_t)row * D_EMB + s * 8);
        }
        asm volatile("cp.async.commit_group;" ::: "memory");
    }

    float d[2][8][4];
    #pragma unroll
    for (int mt = 0; mt < 2; mt++)
        #pragma unroll
        for (int nt = 0; nt < 8; nt++)
            #pragma unroll
            for (int r = 0; r < 4; r++) d[mt][nt][r] = 0.f;

    // ldmatrix lane mapping (x4)
    const int lrow = (lane & 7) + ((lane >> 3) & 1) * 8;  // row within 16-row block
    const int lkh  = (lane >> 4) * 16;                    // k-half byte offset

    for (int c = 0; c < NCHUNKS; c++) {
        // prefetch next chunk
        if (c + 1 < NCHUNKS) {
            int nb = (c + 1) & 1;
            char* bufA = tiles + nb * 2 * TILE_BYTES;
            char* bufB = bufA + TILE_BYTES;
            const __nv_bfloat16* pA = gA + (c + 1) * KCH;
            const __nv_bfloat16* pB = gB + (c + 1) * KCH;
            #pragma unroll
            for (int i = 0; i < 4; i++) {
                int idx = tid + i * NTHREADS;
                int row = idx >> 3, s = idx & 7;
                uint32_t off = sw128((uint32_t)(row * 128 + s * 16));
                cp16(smem_u32(bufA + off), pA + (size_t)row * D_EMB + s * 8);
                cp16(smem_u32(bufB + off), pB + (size_t)row * D_EMB + s * 8);
            }
            asm volatile("cp.async.commit_group;" ::: "memory");
            asm volatile("cp.async.wait_group 1;" ::: "memory");
        } else {
            asm volatile("cp.async.wait_group 0;" ::: "memory");
        }
        __syncthreads();

        int b = c & 1;
        uint32_t abase = smem_u32(tiles + b * 2 * TILE_BYTES);
        uint32_t bbase = abase + TILE_BYTES;

        #pragma unroll
        for (int s = 0; s < 4; s++) {      // 4 k16 steps per chunk
            uint32_t kb = s * 32;
            uint32_t a[2][4];
            #pragma unroll
            for (int mt = 0; mt < 2; mt++) {
                int row = wm * 32 + mt * 16 + lrow;
                ldsm_x4(a[mt], abase + sw128(row * 128 + kb + lkh));
            }
            uint32_t bq[4][4];
            #pragma unroll
            for (int nt2 = 0; nt2 < 4; nt2++) {
                int row = wn * 64 + nt2 * 16 + lrow;
                ldsm_x4(bq[nt2], bbase + sw128(row * 128 + kb + lkh));
            }
            #pragma unroll
            for (int mt = 0; mt < 2; mt++)
                #pragma unroll
                for (int nt = 0; nt < 8; nt++) {
                    int nt2 = nt >> 1, odd = nt & 1;
                    mma16816(d[mt][nt], a[mt], bq[nt2][odd], bq[nt2][odd + 2]);
                }
        }
        __syncthreads();   // protect buffer reuse
    }

    // ---------------- fused epilogue ----------------
    const int qrow = lane >> 2;        // 0..7
    const int qcol = (lane & 3) * 2;   // 0,2,4,6

    int cl[8][2];
    #pragma unroll
    for (int nt = 0; nt < 8; nt++) {
        int j = wn * 64 + nt * 8 + qcol;
        cl[nt][0] = collab[j];
        cl[nt][1] = collab[j + 1];
    }

    #pragma unroll
    for (int mt = 0; mt < 2; mt++) {
        int r0 = wm * 32 + mt * 16 + qrow;
        int r1 = r0 + 8;
        int l0 = rowlab[r0], l1 = rowlab[r1];
        int ig0 = rowbase + r0, ig1 = rowbase + r1;
        float pos0 = 0.f, neg0 = 0.f, pos1 = 0.f, neg1 = 0.f;

        #pragma unroll
        for (int nt = 0; nt < 8; nt++) {
            int jg = colbase + wn * 64 + nt * 8 + qcol;
            #pragma unroll
            for (int e = 0; e < 2; e++) {
                float v0 = d[mt][nt][e];        // row r0
                float v1 = d[mt][nt][2 + e];    // row r1
                int lj = cl[nt][e];
                int jge = jg + e;
                if (lj == l0) { if (jge != ig0) pos0 += __expf(0.5f - v0); }
                else          neg0 += __expf(10.0f * v0 - 5.0f);
                if (lj == l1) { if (jge != ig1) pos1 += __expf(0.5f - v1); }
                else          neg1 += __expf(10.0f * v1 - 5.0f);
            }
        }
        // quad reduce (cols live in lane&3)
        #pragma unroll
        for (int m = 1; m <= 2; m <<= 1) {
            pos0 += __shfl_xor_sync(0xFFFFFFFFu, pos0, m);
            neg0 += __shfl_xor_sync(0xFFFFFFFFu, neg0, m);
            pos1 += __shfl_xor_sync(0xFFFFFFFFu, pos1, m);
            neg1 += __shfl_xor_sync(0xFFFFFFFFu, neg1, m);
        }
        if ((lane & 3) == 0) {
            atomicAdd(&g_pos[ig0], pos0);
            atomicAdd(&g_neg[ig0], neg0);
            atomicAdd(&g_pos[ig1], pos1);
            atomicAdd(&g_neg[ig1], neg1);
        }
    }
}

// ============================================================================
// Kernel 2: finalize — log1p terms, valid mask, mean
// ============================================================================
__global__ void ms_finalize(float* __restrict__ out) {
    __shared__ float sred[512];
    __shared__ int cred[512];
    int t = threadIdx.x;
    float tot = 0.f;
    int cnt = 0;
    for (int r = t; r < N_EMB; r += 512) {
        float p = g_pos[r], q = g_neg[r];
        if (p > 0.f && q > 0.f) {
            tot += log1pf(p) + 0.1f * log1pf(q);   // 1/ALPHA=1, 1/BETA=0.1
            cnt++;
        }
    }
    sred[t] = tot;
    cred[t] = cnt;
    __syncthreads();
    for (int s = 256; s > 0; s >>= 1) {
        if (t < s) { sred[t] += sred[t + s]; cred[t] += cred[t + s]; }
        __syncthreads();
    }
    if (t == 0) out[0] = cred[0] > 0 ? sred[0] / (float)cred[0] : 0.f;
}

// ============================================================================
extern "C" void kernel_launch(void* const* d_in, const int* in_sizes, int n_in,
                              void* d_out, int out_size) {
    const float* emb = (const float*)d_in[0];
    const void* labels = d_in[1];
    float* out = (float*)d_out;

    cudaFuncSetAttribute(ms_main, cudaFuncAttributeMaxDynamicSharedMemorySize, SM_TOTAL);

    ms_labels<<<1, 256>>>(labels);
    ms_prep<<<1024, 256>>>(emb);
    dim3 grid(N_EMB / NTILE, N_EMB / MTILE);   // (32, 32)
    ms_main<<<grid, NTHREADS, SM_TOTAL>>>();
    ms_finalize<<<1, 512>>>(out);
}

// round 4
// speedup vs baseline: 1.5899x; 1.5899x over previous
#include <cuda_runtime.h>
#include <cuda_bf16.h>
#include <cstdint>

// ============================================================================
// MultiSimilarityLoss on GB300 (sm_103a; PTX target compute_103 -> no tcgen05;
// mma.sync bf16 HMMA + ldmatrix + cp.async)
//   sim = E @ E^T symmetric -> only 528 upper-triangular 128x128 tiles.
//   Off-diagonal tiles feed BOTH row-i and row-j accumulators (one exp each).
// ============================================================================

#define N_EMB   4096
#define D_EMB   512
#define MTILE   128
#define NTILE   128
#define KCH     64            // K chunk (64 bf16 = 128B rows)
#define NCHUNKS (D_EMB / KCH) // 8
#define NTHREADS 256
#define NTB     (N_EMB / MTILE)          // 32 tile-blocks per dim
#define NTILES  (NTB * (NTB + 1) / 2)    // 528

// Scratch (no cudaMalloc allowed)
__device__ __nv_bfloat16 g_eb[N_EMB * D_EMB];
__device__ float g_pos[N_EMB];
__device__ float g_neg[N_EMB];
__device__ int   g_lab[N_EMB];

// smem: labels (1KB) + 2 double-buffered A/B tiles (4 x 16KB)
#define SM_LABELS  0
#define SM_TILES   1024
#define TILE_BYTES 16384                 // 128 rows x 128B
#define SM_TOTAL   (1024 + 4 * TILE_BYTES)  // 66560

__device__ __forceinline__ uint32_t smem_u32(const void* p) {
    uint32_t a;
    asm("{ .reg .u64 t; cvta.to.shared.u64 t, %1; cvt.u32.u64 %0, t; }" : "=r"(a) : "l"(p));
    return a;
}

__device__ __forceinline__ uint32_t sw128(uint32_t off) {
    return off ^ ((off >> 3) & 0x70);
}

__device__ __forceinline__ void ldsm_x4(uint32_t* r, uint32_t addr) {
    asm volatile("ldmatrix.sync.aligned.m8n8.x4.shared.b16 {%0,%1,%2,%3}, [%4];"
                 : "=r"(r[0]), "=r"(r[1]), "=r"(r[2]), "=r"(r[3]) : "r"(addr));
}

__device__ __forceinline__ void mma16816(float* d, const uint32_t* a, uint32_t b0, uint32_t b1) {
    asm volatile(
        "mma.sync.aligned.m16n8k16.row.col.f32.bf16.bf16.f32 "
        "{%0,%1,%2,%3}, {%4,%5,%6,%7}, {%8,%9}, {%0,%1,%2,%3};"
        : "+f"(d[0]), "+f"(d[1]), "+f"(d[2]), "+f"(d[3])
        : "r"(a[0]), "r"(a[1]), "r"(a[2]), "r"(a[3]), "r"(b0), "r"(b1));
}

__device__ __forceinline__ void cp16(uint32_t dst, const void* src) {
    asm volatile("cp.async.cg.shared.global [%0], [%1], 16;" :: "r"(dst), "l"(src));
}

// ============================================================================
// Kernel 0: prep — labels decode (block 0), fp32 -> bf16, zero accumulators
// ============================================================================
__global__ void ms_prep(const float* __restrict__ emb, const void* __restrict__ rawlab) {
    int t = threadIdx.x;
    if (blockIdx.x == 0) {
        // dtype-agnostic label decode (JAX x64-disable => int32 in practice)
        __shared__ int s_not64;
        const int* r32 = (const int*)rawlab;
        if (t == 0) s_not64 = 0;
        __syncthreads();
        int nz = 0;
        for (int i = t; i < N_EMB / 2; i += NTHREADS) nz |= r32[2 * i + 1];
        if (nz) atomicOr(&s_not64, 1);
        __syncthreads();
        if (s_not64 == 0) {
            const long long* r64 = (const long long*)rawlab;
            for (int i = t; i < N_EMB; i += NTHREADS) g_lab[i] = (int)r64[i];
        } else {
            for (int i = t; i < N_EMB; i += NTHREADS) g_lab[i] = r32[i];
        }
    }
    int g = blockIdx.x * blockDim.x + t;
    int stride = gridDim.x * blockDim.x;
    const float4* src = (const float4*)emb;
    __nv_bfloat162* dst = (__nv_bfloat162*)g_eb;
    for (int i = g; i < N_EMB * D_EMB / 4; i += stride) {
        float4 v = src[i];
        dst[2 * i]     = __floats2bfloat162_rn(v.x, v.y);
        dst[2 * i + 1] = __floats2bfloat162_rn(v.z, v.w);
    }
    if (g < N_EMB) { g_pos[g] = 0.f; g_neg[g] = 0.f; }
}

// ============================================================================
// Kernel 1: main — upper-triangular 128x128 tiles, dual-sided fused epilogue
// ============================================================================
__global__ __launch_bounds__(NTHREADS) void ms_main() {
    extern __shared__ char smem[];
    int* collab = (int*)(smem + SM_LABELS);        // 128 ints
    int* rowlab = (int*)(smem + SM_LABELS + 512);  // 128 ints
    char* tiles = smem + SM_TILES;

    // decode linear tile id -> (by, bx) with bx >= by (row-major triangle)
    int rem = blockIdx.x;
    int by = 0;
    while (rem >= (NTB - by)) { rem -= (NTB - by); by++; }
    int bx = by + rem;
    const bool isdiag = (bx == by);

    const int tid  = threadIdx.x;
    const int wid  = tid >> 5;
    const int lane = tid & 31;
    const int wm   = wid & 3;   // M offset wm*32
    const int wn   = wid >> 2;  // N offset wn*64
    const int colbase = bx * NTILE;
    const int rowbase = by * MTILE;

    if (tid < 128) collab[tid] = g_lab[colbase + tid];
    else           rowlab[tid - 128] = g_lab[rowbase + tid - 128];

    const __nv_bfloat16* gA = g_eb + (size_t)rowbase * D_EMB;
    const __nv_bfloat16* gB = g_eb + (size_t)colbase * D_EMB;

    // ---- issue chunk 0 loads ----
    {
        char* bufA = tiles;
        char* bufB = tiles + TILE_BYTES;
        #pragma unroll
        for (int i = 0; i < 4; i++) {
            int idx = tid + i * NTHREADS;
            int row = idx >> 3, s = idx & 7;
            uint32_t off = sw128((uint32_t)(row * 128 + s * 16));
            cp16(smem_u32(bufA + off), gA + (size_t)row * D_EMB + s * 8);
            cp16(smem_u32(bufB + off), gB + (size_t)row * D_EMB + s * 8);
        }
        asm volatile("cp.async.commit_group;" ::: "memory");
    }

    float d[2][8][4];
    #pragma unroll
    for (int mt = 0; mt < 2; mt++)
        #pragma unroll
        for (int nt = 0; nt < 8; nt++)
            #pragma unroll
            for (int r = 0; r < 4; r++) d[mt][nt][r] = 0.f;

    const int lrow = (lane & 7) + ((lane >> 3) & 1) * 8;
    const int lkh  = (lane >> 4) * 16;

    for (int c = 0; c < NCHUNKS; c++) {
        if (c + 1 < NCHUNKS) {
            int nb = (c + 1) & 1;
            char* bufA = tiles + nb * 2 * TILE_BYTES;
            char* bufB = bufA + TILE_BYTES;
            const __nv_bfloat16* pA = gA + (c + 1) * KCH;
            const __nv_bfloat16* pB = gB + (c + 1) * KCH;
            #pragma unroll
            for (int i = 0; i < 4; i++) {
                int idx = tid + i * NTHREADS;
                int row = idx >> 3, s = idx & 7;
                uint32_t off = sw128((uint32_t)(row * 128 + s * 16));
                cp16(smem_u32(bufA + off), pA + (size_t)row * D_EMB + s * 8);
                cp16(smem_u32(bufB + off), pB + (size_t)row * D_EMB + s * 8);
            }
            asm volatile("cp.async.commit_group;" ::: "memory");
            asm volatile("cp.async.wait_group 1;" ::: "memory");
        } else {
            asm volatile("cp.async.wait_group 0;" ::: "memory");
        }
        __syncthreads();

        int b = c & 1;
        uint32_t abase = smem_u32(tiles + b * 2 * TILE_BYTES);
        uint32_t bbase = abase + TILE_BYTES;

        #pragma unroll
        for (int s = 0; s < 4; s++) {
            uint32_t kb = s * 32;
            uint32_t a[2][4];
            #pragma unroll
            for (int mt = 0; mt < 2; mt++) {
                int row = wm * 32 + mt * 16 + lrow;
                ldsm_x4(a[mt], abase + sw128(row * 128 + kb + lkh));
            }
            uint32_t bq[4][4];
            #pragma unroll
            for (int nt2 = 0; nt2 < 4; nt2++) {
                int row = wn * 64 + nt2 * 16 + lrow;
                ldsm_x4(bq[nt2], bbase + sw128(row * 128 + kb + lkh));
            }
            #pragma unroll
            for (int mt = 0; mt < 2; mt++)
                #pragma unroll
                for (int nt = 0; nt < 8; nt++) {
                    int nt2 = nt >> 1, odd = nt & 1;
                    mma16816(d[mt][nt], a[mt], bq[nt2][odd], bq[nt2][odd + 2]);
                }
        }
        __syncthreads();
    }

    // ---------------- fused epilogue (dual-sided for off-diag tiles) --------
    const int qrow = lane >> 2;        // 0..7
    const int qcol = (lane & 3) * 2;   // 0,2,4,6

    int cl[8][2];
    #pragma unroll
    for (int nt = 0; nt < 8; nt++) {
        int j = wn * 64 + nt * 8 + qcol;
        cl[nt][0] = collab[j];
        cl[nt][1] = collab[j + 1];
    }

    float cpos[16], cneg[16];
    #pragma unroll
    for (int k = 0; k < 16; k++) { cpos[k] = 0.f; cneg[k] = 0.f; }

    #pragma unroll
    for (int mt = 0; mt < 2; mt++) {
        int r0 = wm * 32 + mt * 16 + qrow;
        int r1 = r0 + 8;
        int l0 = rowlab[r0], l1 = rowlab[r1];
        int ig0 = rowbase + r0, ig1 = rowbase + r1;
        float pos0 = 0.f, neg0 = 0.f, pos1 = 0.f, neg1 = 0.f;

        #pragma unroll
        for (int nt = 0; nt < 8; nt++) {
            int jg = colbase + wn * 64 + nt * 8 + qcol;
            #pragma unroll
            for (int e = 0; e < 2; e++) {
                float v0 = d[mt][nt][e];
                float v1 = d[mt][nt][2 + e];
                int lj = cl[nt][e];
                int jge = jg + e;
                bool eq0 = (lj == l0), eq1 = (lj == l1);
                float e0 = __expf(eq0 ? (0.5f - v0) : (10.0f * v0 - 5.0f));
                float e1 = __expf(eq1 ? (0.5f - v1) : (10.0f * v1 - 5.0f));
                if (eq0) { if (jge != ig0) pos0 += e0; } else neg0 += e0;
                if (eq1) { if (jge != ig1) pos1 += e1; } else neg1 += e1;
                if (!isdiag) {
                    // mirror contribution to row j (i != j guaranteed)
                    int k = nt * 2 + e;
                    if (eq0) cpos[k] += e0; else cneg[k] += e0;
                    if (eq1) cpos[k] += e1; else cneg[k] += e1;
                }
            }
        }
        #pragma unroll
        for (int m = 1; m <= 2; m <<= 1) {
            pos0 += __shfl_xor_sync(0xFFFFFFFFu, pos0, m);
            neg0 += __shfl_xor_sync(0xFFFFFFFFu, neg0, m);
            pos1 += __shfl_xor_sync(0xFFFFFFFFu, pos1, m);
            neg1 += __shfl_xor_sync(0xFFFFFFFFu, neg1, m);
        }
        if ((lane & 3) == 0) {
            atomicAdd(&g_pos[ig0], pos0);
            atomicAdd(&g_neg[ig0], neg0);
            atomicAdd(&g_pos[ig1], pos1);
            atomicAdd(&g_neg[ig1], neg1);
        }
    }

    if (!isdiag) {
        // reduce column sums across the 8 qrow lane-groups (xor 4,8,16)
        #pragma unroll
        for (int k = 0; k < 16; k++) {
            #pragma unroll
            for (int m = 4; m <= 16; m <<= 1) {
                cpos[k] += __shfl_xor_sync(0xFFFFFFFFu, cpos[k], m);
                cneg[k] += __shfl_xor_sync(0xFFFFFFFFu, cneg[k], m);
            }
        }
        if (lane < 4) {
            #pragma unroll
            for (int nt = 0; nt < 8; nt++)
                #pragma unroll
                for (int e = 0; e < 2; e++) {
                    int j = colbase + wn * 64 + nt * 8 + lane * 2 + e;
                    atomicAdd(&g_pos[j], cpos[nt * 2 + e]);
                    atomicAdd(&g_neg[j], cneg[nt * 2 + e]);
                }
        }
    }
}

// ============================================================================
// Kernel 2: finalize — log1p terms, valid mask, mean (shfl-based)
// ============================================================================
__global__ void ms_finalize(float* __restrict__ out) {
    __shared__ float swp[32];
    __shared__ float swc[32];
    int t = threadIdx.x;
    int wid = t >> 5, lane = t & 31;
    float tot = 0.f, cnt = 0.f;
    for (int r = t; r < N_EMB; r += 1024) {
        float p = g_pos[r], q = g_neg[r];
        if (p > 0.f && q > 0.f) {
            tot += log1pf(p) + 0.1f * log1pf(q);
            cnt += 1.f;
        }
    }
    #pragma unroll
    for (int m = 16; m > 0; m >>= 1) {
        tot += __shfl_xor_sync(0xFFFFFFFFu, tot, m);
        cnt += __shfl_xor_sync(0xFFFFFFFFu, cnt, m);
    }
    if (lane == 0) { swp[wid] = tot; swc[wid] = cnt; }
    __syncthreads();
    if (wid == 0) {
        tot = swp[lane];
        cnt = swc[lane];
        #pragma unroll
        for (int m = 16; m > 0; m >>= 1) {
            tot += __shfl_xor_sync(0xFFFFFFFFu, tot, m);
            cnt += __shfl_xor_sync(0xFFFFFFFFu, cnt, m);
        }
        if (lane == 0) out[0] = cnt > 0.f ? tot / cnt : 0.f;
    }
}

// ============================================================================
extern "C" void kernel_launch(void* const* d_in, const int* in_sizes, int n_in,
                              void* d_out, int out_size) {
    const float* emb = (const float*)d_in[0];
    const void* labels = d_in[1];
    float* out = (float*)d_out;

    cudaFuncSetAttribute(ms_main, cudaFuncAttributeMaxDynamicSharedMemorySize, SM_TOTAL);

    ms_prep<<<1024, NTHREADS>>>(emb, labels);
    ms_main<<<NTILES, NTHREADS, SM_TOTAL>>>();
    ms_finalize<<<1, 1024>>>(out);
}